// round 14
// baseline (speedup 1.0000x reference)
#include <cuda_runtime.h>
#include <cuda_fp16.h>
#include <mma.h>
#include <math.h>

using namespace nvcuda;

#define NPTS 65536
#define CDIM 256
#define KWIN 32
#define NWIN 2048
#define LXYZ 40
#define LRGB 32
#define QSF 4.0f
#define CQSF 8.0f
#define QK_SCALE 0.25f

// half-table layout offsets (in halfs). Row layout TRANSPOSED: [row][c][h][8]
#define T_KX 0
#define T_QX 30720
#define T_VX 61440
#define T_KR 92160
#define T_QR 116736
#define T_VR 141312
#define T_TOT 165888

// Scratch (allocation-free rule: device globals)
__device__ float g_qkv[(size_t)NPTS * 768];
__device__ float g_mid[(size_t)NPTS * CDIM];
__device__ __align__(16) __half g_tabh[T_TOT];

// ---------------------------------------------------------------------------
// Convert fp32 tables to fp16 with transposed row layout [row][c][h][8halfs]
// ---------------------------------------------------------------------------
__global__ void cvt_tabs(const float* __restrict__ kx, const float* __restrict__ qx,
                         const float* __restrict__ vx, const float* __restrict__ kr,
                         const float* __restrict__ qr, const float* __restrict__ vr)
{
    int i = blockIdx.x * 256 + threadIdx.x;
    int dst = (i & ~255) | ((i & 8) << 4) | ((i & 240) >> 1) | (i & 7);
    if (i < 30720) {
        g_tabh[T_KX + dst] = __float2half(kx[i]);
        g_tabh[T_QX + dst] = __float2half(qx[i]);
        g_tabh[T_VX + dst] = __float2half(vx[i]);
    }
    if (i < 24576) {
        g_tabh[T_KR + dst] = __float2half(kr[i]);
        g_tabh[T_QR + dst] = __float2half(qr[i]);
        g_tabh[T_VR + dst] = __float2half(vr[i]);
    }
}

// no-op: keeps win_attn at launch #4 (ncu capture slot)
__global__ void nil_k() {}

// ---------------------------------------------------------------------------
// fp16 tensor-core GEMM (fp32 accumulate): C[M,N] = A[M,K] @ W[N,K]^T + bias
// 128x128 CTA tile, 8 warps x (32x64), BK=32, double-buffered fp16 smem.
// ---------------------------------------------------------------------------
#define HS 40   // padded smem row stride (halfs)

__global__ __launch_bounds__(256, 2) void gemm_fp16(
    const float* __restrict__ A, const float* __restrict__ Wm,
    const float* __restrict__ bias, float* __restrict__ Cm,
    int M, int N, int Kd)
{
    __shared__ __align__(16) __half As[2][128 * HS];
    __shared__ __align__(16) __half Bs[2][128 * HS];
    __shared__ __align__(16) float scratch[8][256];

    const int tid = threadIdx.x;
    const int wid = tid >> 5;
    const int lane = tid & 31;
    const int brow = blockIdx.y * 128;
    const int bcol = blockIdx.x * 128;
    const int m0 = (wid >> 1) * 32;
    const int n0 = (wid & 1) * 64;

    const int lrow = tid >> 1;
    const int lcb = (tid & 1) * 16;
    const float* Ap = A + (size_t)(brow + lrow) * Kd + lcb;
    const float* Wp = Wm + (size_t)(bcol + lrow) * Kd + lcb;

    wmma::fragment<wmma::accumulator, 16, 16, 16, float> acc[2][4];
#pragma unroll
    for (int mi = 0; mi < 2; mi++)
#pragma unroll
        for (int ni = 0; ni < 4; ni++) wmma::fill_fragment(acc[mi][ni], 0.f);

#define CVT16(dst, f0, f1, f2, f3) do { \
        __half2 h0 = __float22half2_rn(make_float2((f0).x, (f0).y)); \
        __half2 h1 = __float22half2_rn(make_float2((f0).z, (f0).w)); \
        __half2 h2 = __float22half2_rn(make_float2((f1).x, (f1).y)); \
        __half2 h3 = __float22half2_rn(make_float2((f1).z, (f1).w)); \
        __half2 h4 = __float22half2_rn(make_float2((f2).x, (f2).y)); \
        __half2 h5 = __float22half2_rn(make_float2((f2).z, (f2).w)); \
        __half2 h6 = __float22half2_rn(make_float2((f3).x, (f3).y)); \
        __half2 h7 = __float22half2_rn(make_float2((f3).z, (f3).w)); \
        ((__half2*)(dst))[0] = h0; ((__half2*)(dst))[1] = h1; \
        ((__half2*)(dst))[2] = h2; ((__half2*)(dst))[3] = h3; \
        ((__half2*)(dst))[4] = h4; ((__half2*)(dst))[5] = h5; \
        ((__half2*)(dst))[6] = h6; ((__half2*)(dst))[7] = h7; } while (0)

    {
        float4 a0 = *(const float4*)Ap,       a1 = *(const float4*)(Ap + 4);
        float4 a2 = *(const float4*)(Ap + 8), a3 = *(const float4*)(Ap + 12);
        float4 w0 = *(const float4*)Wp,       w1 = *(const float4*)(Wp + 4);
        float4 w2 = *(const float4*)(Wp + 8), w3 = *(const float4*)(Wp + 12);
        CVT16(&As[0][lrow * HS + lcb], a0, a1, a2, a3);
        CVT16(&Bs[0][lrow * HS + lcb], w0, w1, w2, w3);
    }
    __syncthreads();

    const int nT = Kd / 32;
    for (int kt = 0; kt < nT; kt++) {
        const int buf = kt & 1;
        float4 a0, a1, a2, a3, w0, w1, w2, w3;
        const bool more = (kt + 1 < nT);
        if (more) {
            const float* Ax = Ap + (kt + 1) * 32;
            const float* Wx = Wp + (kt + 1) * 32;
            a0 = *(const float4*)Ax;       a1 = *(const float4*)(Ax + 4);
            a2 = *(const float4*)(Ax + 8); a3 = *(const float4*)(Ax + 12);
            w0 = *(const float4*)Wx;       w1 = *(const float4*)(Wx + 4);
            w2 = *(const float4*)(Wx + 8); w3 = *(const float4*)(Wx + 12);
        }
#pragma unroll
        for (int ks = 0; ks < 2; ks++) {
            wmma::fragment<wmma::matrix_a, 16, 16, 16, __half, wmma::row_major> af[2];
            wmma::fragment<wmma::matrix_b, 16, 16, 16, __half, wmma::col_major> bf[4];
#pragma unroll
            for (int mi = 0; mi < 2; mi++)
                wmma::load_matrix_sync(af[mi],
                    &As[buf][(m0 + 16 * mi) * HS + ks * 16], HS);
#pragma unroll
            for (int ni = 0; ni < 4; ni++)
                wmma::load_matrix_sync(bf[ni],
                    &Bs[buf][(n0 + 16 * ni) * HS + ks * 16], HS);
#pragma unroll
            for (int mi = 0; mi < 2; mi++)
#pragma unroll
                for (int ni = 0; ni < 4; ni++)
                    wmma::mma_sync(acc[mi][ni], af[mi], bf[ni], acc[mi][ni]);
        }
        if (more) {
            const int b2 = buf ^ 1;
            CVT16(&As[b2][lrow * HS + lcb], a0, a1, a2, a3);
            CVT16(&Bs[b2][lrow * HS + lcb], w0, w1, w2, w3);
        }
        __syncthreads();
    }
#undef CVT16

#pragma unroll
    for (int mi = 0; mi < 2; mi++) {
#pragma unroll
        for (int ni = 0; ni < 4; ni++) {
            wmma::store_matrix_sync(scratch[wid], acc[mi][ni], 16,
                                    wmma::mem_row_major);
            __syncwarp();
#pragma unroll
            for (int e = 0; e < 8; e++) {
                int id = e * 32 + lane;
                int rr = id >> 4, cc = id & 15;
                int col = bcol + n0 + 16 * ni + cc;
                Cm[(size_t)(brow + m0 + 16 * mi + rr) * N + col] =
                    scratch[wid][rr * 16 + cc] + __ldg(&bias[col]);
            }
            __syncwarp();
        }
    }
}

// ---------------------------------------------------------------------------
// Windowed attention: fused single-pass, fp16 tables + fp16 K/V smem.
// Main q.k dot reuses the K registers loaded for the table dot (no fp32 K).
// launch_bounds(256,2): regs stay 128, NO spills (the r7 mistake was (256,3)).
// ---------------------------------------------------------------------------
struct H8 { uint4 u; };
__device__ __forceinline__ H8 ldt(const __half* __restrict__ p) {
    H8 r; r.u = *(const uint4*)p; return r;
}
__device__ __forceinline__ __half2 lane(const H8& a, int l) {
    unsigned w = (l == 0) ? a.u.x : (l == 1) ? a.u.y : (l == 2) ? a.u.z : a.u.w;
    return *reinterpret_cast<const __half2*>(&w);
}
__device__ __forceinline__ __half2 sum6(const H8& a0, const H8& a1, const H8& a2,
                                        const H8& a3, const H8& a4, const H8& a5, int l) {
    return __hadd2(__hadd2(__hadd2(lane(a0, l), lane(a1, l)),
                           __hadd2(lane(a2, l), lane(a3, l))),
                   __hadd2(lane(a4, l), lane(a5, l)));
}

// smem layout:
//   skh    [32*256] halfs @ half-off 0      (16 KB)
//   svh    [32*256] halfs @ half-off 8192   (16 KB)
//   scoord [192] floats   @ float-off 8192
//   spt    [32] int       @ float-off 8384
//   sidx2  [1024] uint2   @ float-off 8416  (ends 10464)
#define ATTN_SMEM_FLOATS 10464
#define ATTN_SMEM_BYTES (ATTN_SMEM_FLOATS * 4)

__global__ __launch_bounds__(256, 2) void win_attn(
    const float* __restrict__ n_coords, const int* __restrict__ n2n)
{
    extern __shared__ float smem[];
    __half* skh = (__half*)smem;
    __half* svh = skh + 8192;
    float* scoord = smem + 8192;
    int* spt = (int*)(smem + 8384);
    uint2* sidx2 = (uint2*)(smem + 8416);

    const int tid = threadIdx.x;
    const int w = blockIdx.x;

    if (tid < KWIN) spt[tid] = n2n[w * KWIN + tid];
    __syncthreads();

    if (tid < 192) {
        int i = tid / 6, d = tid % 6;
        float s = (d < 3) ? QSF : CQSF;
        scoord[tid] = n_coords[(size_t)spt[i] * 6 + d] * s;
    }
    // stage K and V as fp16 (coalesced fp32 gmem reads)
    for (int j = 0; j < KWIN; ++j) {
        size_t base = (size_t)spt[j] * 768;
        skh[j * 256 + tid] = __float2half(g_qkv[base + 256 + tid]);
        svh[j * 256 + tid] = __float2half(g_qkv[base + 512 + tid]);
    }
    __syncthreads();

    // packed relative indices per (i,j)
#pragma unroll
    for (int r = 0; r < 4; ++r) {
        int p = r * 256 + tid;
        int i = p >> 5, j = p & 31;
        const float* ci = scoord + i * 6;
        const float* cj = scoord + j * 6;
        int l[6];
#pragma unroll
        for (int d = 0; d < 3; d++) {
            int v = (int)floorf(ci[d] - cj[d]) + LXYZ / 2;
            l[d] = min(max(v, 0), LXYZ - 1);
        }
#pragma unroll
        for (int d = 0; d < 3; d++) {
            int v = (int)floorf(ci[3 + d] - cj[3 + d]) + LRGB / 2;
            l[3 + d] = min(max(v, 0), LRGB - 1);
        }
        unsigned lo = (unsigned)l[0] | ((unsigned)l[1] << 8) |
                      ((unsigned)l[2] << 16) | ((unsigned)l[3] << 24);
        unsigned hi = (unsigned)l[4] | ((unsigned)l[5] << 8);
        sidx2[p] = make_uint2(lo, hi);
    }
    __syncthreads();

    // each thread owns rows (i,h); 512 rows total, 2 per thread
    for (int r = 0; r < 2; ++r) {
        const int row = r * 256 + tid;
        const int i = row >> 4;
        const int h = row & 15;
        const int hb = h * 16;   // K/V smem base (halfs) & q/out base (floats)
        const int h8 = h * 8;    // transposed table base (halfs)
        const int pt = spt[i];

        const __half* tKX = g_tabh + T_KX + h8;
        const __half* tQX = g_tabh + T_QX + h8;
        const __half* tVX = g_tabh + T_VX + h8;
        const __half* tKR = g_tabh + T_KR + h8;
        const __half* tQR = g_tabh + T_QR + h8;
        const __half* tVR = g_tabh + T_VR + h8;

        // q row (scaled): fp32 + half2 copy
        float qf[16];
        __half2 qh[8];
        {
            const float4* qp = (const float4*)(g_qkv + (size_t)pt * 768 + hb);
#pragma unroll
            for (int t = 0; t < 4; t++) {
                float4 v = qp[t];
                qf[t * 4 + 0] = v.x * QK_SCALE; qf[t * 4 + 1] = v.y * QK_SCALE;
                qf[t * 4 + 2] = v.z * QK_SCALE; qf[t * 4 + 3] = v.w * QK_SCALE;
            }
#pragma unroll
            for (int k = 0; k < 8; k++)
                qh[k] = __floats2half2_rn(qf[2 * k], qf[2 * k + 1]);
        }

        // softmax baseline: main dot vs j=0 (shift only; weights unchanged)
        float bshift = 0.f;
        {
            H8 k0a = ldt(skh + hb);
            H8 k0b = ldt(skh + hb + 8);
#pragma unroll
            for (int l = 0; l < 4; l++) {
                float2 fa = __half22float2(lane(k0a, l));
                float2 fb = __half22float2(lane(k0b, l));
                bshift += qf[2 * l] * fa.x + qf[2 * l + 1] * fa.y +
                          qf[8 + 2 * l] * fb.x + qf[9 + 2 * l] * fb.y;
            }
        }

        float ssum = 0.f;
        float of[16];
#pragma unroll
        for (int e = 0; e < 16; e++) of[e] = 0.f;

        // ---- fused single pass over j ----
        for (int j = 0; j < KWIN; ++j) {
            const uint2 pk = sidx2[i * 32 + j];
            const int r0 = (int)(pk.x & 255) << 8;
            const int r1 = (int)(40 + ((pk.x >> 8) & 255)) << 8;
            const int r2 = (int)(80 + ((pk.x >> 16) & 255)) << 8;
            const int r3 = (int)(pk.x >> 24) << 8;
            const int r4 = (int)(32 + (pk.y & 255)) << 8;
            const int r5 = (int)(64 + ((pk.y >> 8) & 255)) << 8;

            // K row (fp16 -> fp32 main dot, registers reused for table dot)
            H8 kka = ldt(skh + j * 256 + hb);
            H8 kkb = ldt(skh + j * 256 + hb + 8);
            float facc = 0.f;
#pragma unroll
            for (int l = 0; l < 4; l++) {
                float2 fa = __half22float2(lane(kka, l));
                float2 fb = __half22float2(lane(kkb, l));
                facc += qf[2 * l] * fa.x + qf[2 * l + 1] * fa.y +
                        qf[8 + 2 * l] * fb.x + qf[9 + 2 * l] * fb.y;
            }

            // half table logit part (two 8-half chunks)
#pragma unroll
            for (int c = 0; c < 2; c++) {
                const int co = c << 7;
                H8 a0 = ldt(tKX + r0 + co), a1 = ldt(tKX + r1 + co),
                   a2 = ldt(tKX + r2 + co), a3 = ldt(tKR + r3 + co),
                   a4 = ldt(tKR + r4 + co), a5 = ldt(tKR + r5 + co);
                H8 b0 = ldt(tQX + r0 + co), b1 = ldt(tQX + r1 + co),
                   b2 = ldt(tQX + r2 + co), b3 = ldt(tQR + r3 + co),
                   b4 = ldt(tQR + r4 + co), b5 = ldt(tQR + r5 + co);
                const H8& kk = c ? kkb : kka;
                __half2 hq = __float2half2_rn(0.f);
                __half2 hk = hq;
#pragma unroll
                for (int l = 0; l < 4; l++) {
                    __half2 qs = sum6(a0, a1, a2, a3, a4, a5, l);
                    __half2 ks = sum6(b0, b1, b2, b3, b4, b5, l);
                    hq = __hfma2(qh[c * 4 + l], qs, hq);
                    hk = __hfma2(lane(kk, l), ks, hk);
                }
                float2 f = __half22float2(__hadd2(hq, hk));
                facc += f.x + f.y;
            }

            const float a = __expf(facc - bshift);
            ssum += a;

            // value side: fp32 accumulate of a*(v + sum6(vtab)), V fp16 smem
            H8 vva = ldt(svh + j * 256 + hb);
            H8 vvb = ldt(svh + j * 256 + hb + 8);
#pragma unroll
            for (int c = 0; c < 2; c++) {
                const int co = c << 7;
                H8 v0 = ldt(tVX + r0 + co), v1 = ldt(tVX + r1 + co),
                   v2 = ldt(tVX + r2 + co), v3 = ldt(tVR + r3 + co),
                   v4 = ldt(tVR + r4 + co), v5 = ldt(tVR + r5 + co);
                const H8& vv = c ? vvb : vva;
                float* o = of + c * 8;
#pragma unroll
                for (int l = 0; l < 4; l++) {
                    float2 vf = __half22float2(lane(vv, l));
                    float2 tf = __half22float2(sum6(v0, v1, v2, v3, v4, v5, l));
                    o[2 * l + 0] += a * (vf.x + tf.x);
                    o[2 * l + 1] += a * (vf.y + tf.y);
                }
            }
        }

        const float inv = 1.0f / ssum;
        float4* op = (float4*)(g_mid + (size_t)pt * CDIM + hb);
#pragma unroll
        for (int t = 0; t < 4; t++)
            op[t] = make_float4(of[4 * t] * inv, of[4 * t + 1] * inv,
                                of[4 * t + 2] * inv, of[4 * t + 3] * inv);
    }
}

// ---------------------------------------------------------------------------
extern "C" void kernel_launch(void* const* d_in, const int* in_sizes, int n_in,
                              void* d_out, int out_size)
{
    const float* feats    = (const float*)d_in[0];
    const float* n_coords = (const float*)d_in[1];
    const int*   n2n      = (const int*)d_in[2];
    const float* q_xyz    = (const float*)d_in[3];
    const float* k_xyz    = (const float*)d_in[4];
    const float* v_xyz    = (const float*)d_in[5];
    const float* q_rgb    = (const float*)d_in[6];
    const float* k_rgb    = (const float*)d_in[7];
    const float* v_rgb    = (const float*)d_in[8];
    const float* qkv_w    = (const float*)d_in[9];
    const float* qkv_b    = (const float*)d_in[10];
    const float* proj_w   = (const float*)d_in[11];
    const float* proj_b   = (const float*)d_in[12];
    float* out = (float*)d_out;

    float *qkv_p = nullptr, *mid_p = nullptr;
    cudaGetSymbolAddress((void**)&qkv_p, g_qkv);
    cudaGetSymbolAddress((void**)&mid_p, g_mid);

    cudaFuncSetAttribute(win_attn, cudaFuncAttributeMaxDynamicSharedMemorySize,
                         ATTN_SMEM_BYTES);

    // 1) table conversion
    cvt_tabs<<<120, 256>>>(k_xyz, q_xyz, v_xyz, k_rgb, q_rgb, v_rgb);

    // 2) QKV projection (fp16 tensor cores, fp32 accumulate)
    dim3 g1(768 / 128, NPTS / 128);
    gemm_fp16<<<g1, 256>>>(feats, qkv_w, qkv_b, qkv_p, NPTS, 768, CDIM);

    // 3) no-op so win_attn is the 4th launch (ncu capture slot)
    nil_k<<<1, 32>>>();

    // 4) windowed attention (fp16 K/V smem, no-spill)
    win_attn<<<NWIN, 256, ATTN_SMEM_BYTES>>>(n_coords, n2n);

    // 5) output projection (fp16 tensor cores, fp32 accumulate)
    dim3 g2(CDIM / 128, NPTS / 128);
    gemm_fp16<<<g2, 256>>>(mid_p, proj_w, proj_b, out, NPTS, CDIM, CDIM);
}

// round 15
// speedup vs baseline: 1.0352x; 1.0352x over previous
#include <cuda_runtime.h>
#include <cuda_fp16.h>
#include <mma.h>
#include <math.h>

using namespace nvcuda;

#define NPTS 65536
#define CDIM 256
#define KWIN 32
#define NWIN 2048
#define LXYZ 40
#define LRGB 32
#define QSF 4.0f
#define CQSF 8.0f
#define QK_SCALE 0.25f

// half-table layout offsets (in halfs). Row layout TRANSPOSED: [row][c][h][8]
#define T_KX 0
#define T_QX 30720
#define T_VX 61440
#define T_KR 92160
#define T_QR 116736
#define T_VR 141312
#define T_TOT 165888

// Scratch (allocation-free rule: device globals)
__device__ float g_qf[(size_t)NPTS * 256];          // prescaled q, fp32
__device__ __align__(16) __half g_kh[(size_t)NPTS * 256];  // k, fp16
__device__ __align__(16) __half g_vh[(size_t)NPTS * 256];  // v, fp16
__device__ float g_mid[(size_t)NPTS * CDIM];
__device__ __align__(16) __half g_tabh[T_TOT];

// ---------------------------------------------------------------------------
// Convert fp32 tables to fp16 with transposed row layout [row][c][h][8halfs]
// ---------------------------------------------------------------------------
__global__ void cvt_tabs(const float* __restrict__ kx, const float* __restrict__ qx,
                         const float* __restrict__ vx, const float* __restrict__ kr,
                         const float* __restrict__ qr, const float* __restrict__ vr)
{
    int i = blockIdx.x * 256 + threadIdx.x;
    int dst = (i & ~255) | ((i & 8) << 4) | ((i & 240) >> 1) | (i & 7);
    if (i < 30720) {
        g_tabh[T_KX + dst] = __float2half(kx[i]);
        g_tabh[T_QX + dst] = __float2half(qx[i]);
        g_tabh[T_VX + dst] = __float2half(vx[i]);
    }
    if (i < 24576) {
        g_tabh[T_KR + dst] = __float2half(kr[i]);
        g_tabh[T_QR + dst] = __float2half(qr[i]);
        g_tabh[T_VR + dst] = __float2half(vr[i]);
    }
}

// no-op: keeps win_attn at launch #4 (ncu capture slot)
__global__ void nil_k() {}

// ---------------------------------------------------------------------------
// fp16 tensor-core GEMM (fp32 accumulate): C[M,N] = A[M,K] @ W[N,K]^T + bias
// split=1 (QKV): col<256 -> g_qf (fp32, prescaled); <512 -> g_kh; else g_vh
// ---------------------------------------------------------------------------
#define HS 40   // padded smem row stride (halfs)

__global__ __launch_bounds__(256, 2) void gemm_fp16(
    const float* __restrict__ A, const float* __restrict__ Wm,
    const float* __restrict__ bias, float* __restrict__ Cm,
    int M, int N, int Kd, int split)
{
    __shared__ __align__(16) __half As[2][128 * HS];
    __shared__ __align__(16) __half Bs[2][128 * HS];
    __shared__ __align__(16) float scratch[8][256];

    const int tid = threadIdx.x;
    const int wid = tid >> 5;
    const int lane = tid & 31;
    const int brow = blockIdx.y * 128;
    const int bcol = blockIdx.x * 128;
    const int m0 = (wid >> 1) * 32;
    const int n0 = (wid & 1) * 64;

    const int lrow = tid >> 1;
    const int lcb = (tid & 1) * 16;
    const float* Ap = A + (size_t)(brow + lrow) * Kd + lcb;
    const float* Wp = Wm + (size_t)(bcol + lrow) * Kd + lcb;

    wmma::fragment<wmma::accumulator, 16, 16, 16, float> acc[2][4];
#pragma unroll
    for (int mi = 0; mi < 2; mi++)
#pragma unroll
        for (int ni = 0; ni < 4; ni++) wmma::fill_fragment(acc[mi][ni], 0.f);

#define CVT16(dst, f0, f1, f2, f3) do { \
        __half2 h0 = __float22half2_rn(make_float2((f0).x, (f0).y)); \
        __half2 h1 = __float22half2_rn(make_float2((f0).z, (f0).w)); \
        __half2 h2 = __float22half2_rn(make_float2((f1).x, (f1).y)); \
        __half2 h3 = __float22half2_rn(make_float2((f1).z, (f1).w)); \
        __half2 h4 = __float22half2_rn(make_float2((f2).x, (f2).y)); \
        __half2 h5 = __float22half2_rn(make_float2((f2).z, (f2).w)); \
        __half2 h6 = __float22half2_rn(make_float2((f3).x, (f3).y)); \
        __half2 h7 = __float22half2_rn(make_float2((f3).z, (f3).w)); \
        ((__half2*)(dst))[0] = h0; ((__half2*)(dst))[1] = h1; \
        ((__half2*)(dst))[2] = h2; ((__half2*)(dst))[3] = h3; \
        ((__half2*)(dst))[4] = h4; ((__half2*)(dst))[5] = h5; \
        ((__half2*)(dst))[6] = h6; ((__half2*)(dst))[7] = h7; } while (0)

    {
        float4 a0 = *(const float4*)Ap,       a1 = *(const float4*)(Ap + 4);
        float4 a2 = *(const float4*)(Ap + 8), a3 = *(const float4*)(Ap + 12);
        float4 w0 = *(const float4*)Wp,       w1 = *(const float4*)(Wp + 4);
        float4 w2 = *(const float4*)(Wp + 8), w3 = *(const float4*)(Wp + 12);
        CVT16(&As[0][lrow * HS + lcb], a0, a1, a2, a3);
        CVT16(&Bs[0][lrow * HS + lcb], w0, w1, w2, w3);
    }
    __syncthreads();

    const int nT = Kd / 32;
    for (int kt = 0; kt < nT; kt++) {
        const int buf = kt & 1;
        float4 a0, a1, a2, a3, w0, w1, w2, w3;
        const bool more = (kt + 1 < nT);
        if (more) {
            const float* Ax = Ap + (kt + 1) * 32;
            const float* Wx = Wp + (kt + 1) * 32;
            a0 = *(const float4*)Ax;       a1 = *(const float4*)(Ax + 4);
            a2 = *(const float4*)(Ax + 8); a3 = *(const float4*)(Ax + 12);
            w0 = *(const float4*)Wx;       w1 = *(const float4*)(Wx + 4);
            w2 = *(const float4*)(Wx + 8); w3 = *(const float4*)(Wx + 12);
        }
#pragma unroll
        for (int ks = 0; ks < 2; ks++) {
            wmma::fragment<wmma::matrix_a, 16, 16, 16, __half, wmma::row_major> af[2];
            wmma::fragment<wmma::matrix_b, 16, 16, 16, __half, wmma::col_major> bf[4];
#pragma unroll
            for (int mi = 0; mi < 2; mi++)
                wmma::load_matrix_sync(af[mi],
                    &As[buf][(m0 + 16 * mi) * HS + ks * 16], HS);
#pragma unroll
            for (int ni = 0; ni < 4; ni++)
                wmma::load_matrix_sync(bf[ni],
                    &Bs[buf][(n0 + 16 * ni) * HS + ks * 16], HS);
#pragma unroll
            for (int mi = 0; mi < 2; mi++)
#pragma unroll
                for (int ni = 0; ni < 4; ni++)
                    wmma::mma_sync(acc[mi][ni], af[mi], bf[ni], acc[mi][ni]);
        }
        if (more) {
            const int b2 = buf ^ 1;
            CVT16(&As[b2][lrow * HS + lcb], a0, a1, a2, a3);
            CVT16(&Bs[b2][lrow * HS + lcb], w0, w1, w2, w3);
        }
        __syncthreads();
    }
#undef CVT16

#pragma unroll
    for (int mi = 0; mi < 2; mi++) {
#pragma unroll
        for (int ni = 0; ni < 4; ni++) {
            wmma::store_matrix_sync(scratch[wid], acc[mi][ni], 16,
                                    wmma::mem_row_major);
            __syncwarp();
#pragma unroll
            for (int e = 0; e < 8; e++) {
                int id = e * 32 + lane;
                int rr = id >> 4, cc = id & 15;
                int col = bcol + n0 + 16 * ni + cc;
                int row = brow + m0 + 16 * mi + rr;
                float val = scratch[wid][rr * 16 + cc] + __ldg(&bias[col]);
                if (!split) {
                    Cm[(size_t)row * N + col] = val;
                } else if (col < 256) {
                    g_qf[(size_t)row * 256 + col] = val * QK_SCALE;
                } else if (col < 512) {
                    g_kh[(size_t)row * 256 + (col - 256)] = __float2half(val);
                } else {
                    g_vh[(size_t)row * 256 + (col - 512)] = __float2half(val);
                }
            }
            __syncwarp();
        }
    }
}

// ---------------------------------------------------------------------------
// Windowed attention: fp32 K smem (staged from fp16) + fp16 V smem + skh.
// smem 83KB/CTA -> larger L1D carveout -> table hits move L2 -> L1.
// ---------------------------------------------------------------------------
struct H8 { uint4 u; };
__device__ __forceinline__ H8 ldt(const __half* __restrict__ p) {
    H8 r; r.u = *(const uint4*)p; return r;
}
__device__ __forceinline__ __half2 lane(const H8& a, int l) {
    unsigned w = (l == 0) ? a.u.x : (l == 1) ? a.u.y : (l == 2) ? a.u.z : a.u.w;
    return *reinterpret_cast<const __half2*>(&w);
}
__device__ __forceinline__ __half2 sum6(const H8& a0, const H8& a1, const H8& a2,
                                        const H8& a3, const H8& a4, const H8& a5, int l) {
    return __hadd2(__hadd2(__hadd2(lane(a0, l), lane(a1, l)),
                           __hadd2(lane(a2, l), lane(a3, l))),
                   __hadd2(lane(a4, l), lane(a5, l)));
}

// smem layout (float offsets):
//   sk     [32*320] fp32 @ 0..10240  (h-stride 20, conflict-free LDS.128)
//   scoord [192]         @ 10240
//   spt    [32] int      @ 10432
//   sidx2  [1024] uint2  @ 10464..12512
//   skh    [8192] halfs  @ 12512..16608
//   svh    [8192] halfs  @ 16608..20704
#define ATTN_SMEM_FLOATS 20704
#define ATTN_SMEM_BYTES (ATTN_SMEM_FLOATS * 4)

__global__ __launch_bounds__(256, 2) void win_attn(
    const float* __restrict__ n_coords, const int* __restrict__ n2n)
{
    extern __shared__ float smem[];
    float* sk = smem;
    float* scoord = smem + 10240;
    int* spt = (int*)(smem + 10432);
    uint2* sidx2 = (uint2*)(smem + 10464);
    __half* skh = (__half*)(smem + 12512);
    __half* svh = (__half*)(smem + 16608);

    const int tid = threadIdx.x;
    const int w = blockIdx.x;

    if (tid < KWIN) spt[tid] = n2n[w * KWIN + tid];
    __syncthreads();

    if (tid < 192) {
        int i = tid / 6, d = tid % 6;
        float s = (d < 3) ? QSF : CQSF;
        scoord[tid] = n_coords[(size_t)spt[i] * 6 + d] * s;
    }
    // stage K (fp16 source -> fp32 padded + fp16 copy) and V (fp16)
    {
        const int h = tid >> 4, c = tid & 15;
        for (int j = 0; j < KWIN; ++j) {
            size_t base = (size_t)spt[j] * 256;
            __half kh = g_kh[base + tid];
            sk[j * 320 + h * 20 + c] = __half2float(kh);
            skh[j * 256 + tid] = kh;
            svh[j * 256 + tid] = g_vh[base + tid];
        }
    }
    __syncthreads();

    // packed relative indices per (i,j)
#pragma unroll
    for (int r = 0; r < 4; ++r) {
        int p = r * 256 + tid;
        int i = p >> 5, j = p & 31;
        const float* ci = scoord + i * 6;
        const float* cj = scoord + j * 6;
        int l[6];
#pragma unroll
        for (int d = 0; d < 3; d++) {
            int v = (int)floorf(ci[d] - cj[d]) + LXYZ / 2;
            l[d] = min(max(v, 0), LXYZ - 1);
        }
#pragma unroll
        for (int d = 0; d < 3; d++) {
            int v = (int)floorf(ci[3 + d] - cj[3 + d]) + LRGB / 2;
            l[3 + d] = min(max(v, 0), LRGB - 1);
        }
        unsigned lo = (unsigned)l[0] | ((unsigned)l[1] << 8) |
                      ((unsigned)l[2] << 16) | ((unsigned)l[3] << 24);
        unsigned hi = (unsigned)l[4] | ((unsigned)l[5] << 8);
        sidx2[p] = make_uint2(lo, hi);
    }
    __syncthreads();

    // each thread owns rows (i,h); 512 rows total, 2 per thread
    for (int r = 0; r < 2; ++r) {
        const int row = r * 256 + tid;
        const int i = row >> 4;
        const int h = row & 15;
        const int hb = h * 16;
        const int h8 = h * 8;
        const int pt = spt[i];

        const __half* tKX = g_tabh + T_KX + h8;
        const __half* tQX = g_tabh + T_QX + h8;
        const __half* tVX = g_tabh + T_VX + h8;
        const __half* tKR = g_tabh + T_KR + h8;
        const __half* tQR = g_tabh + T_QR + h8;
        const __half* tVR = g_tabh + T_VR + h8;

        // q row (already scaled): fp32 + half2 copy
        float qf[16];
        __half2 qh[8];
        {
            const float4* qp = (const float4*)(g_qf + (size_t)pt * 256 + hb);
#pragma unroll
            for (int t = 0; t < 4; t++) {
                float4 v = qp[t];
                qf[t * 4 + 0] = v.x; qf[t * 4 + 1] = v.y;
                qf[t * 4 + 2] = v.z; qf[t * 4 + 3] = v.w;
            }
#pragma unroll
            for (int k = 0; k < 8; k++)
                qh[k] = __floats2half2_rn(qf[2 * k], qf[2 * k + 1]);
        }

        // softmax baseline from j=0 main dot
        float bshift = 0.f;
        {
            const float* k0 = sk + h * 20;
#pragma unroll
            for (int t = 0; t < 4; t++) {
                float4 kv = *(const float4*)(k0 + 4 * t);
                bshift += qf[4 * t + 0] * kv.x + qf[4 * t + 1] * kv.y +
                          qf[4 * t + 2] * kv.z + qf[4 * t + 3] * kv.w;
            }
        }

        float ssum = 0.f;
        float of[16];
#pragma unroll
        for (int e = 0; e < 16; e++) of[e] = 0.f;

        for (int j = 0; j < KWIN; ++j) {
            const uint2 pk = sidx2[i * 32 + j];
            const int r0 = (int)(pk.x & 255) << 8;
            const int r1 = (int)(40 + ((pk.x >> 8) & 255)) << 8;
            const int r2 = (int)(80 + ((pk.x >> 16) & 255)) << 8;
            const int r3 = (int)(pk.x >> 24) << 8;
            const int r4 = (int)(32 + (pk.y & 255)) << 8;
            const int r5 = (int)(64 + ((pk.y >> 8) & 255)) << 8;

            // fp32 main q.k dot (sk: fp32, conflict-free)
            const float* kj = sk + j * 320 + h * 20;
            float facc = 0.f;
#pragma unroll
            for (int t = 0; t < 4; t++) {
                float4 kv = *(const float4*)(kj + 4 * t);
                facc += qf[4 * t + 0] * kv.x + qf[4 * t + 1] * kv.y +
                        qf[4 * t + 2] * kv.z + qf[4 * t + 3] * kv.w;
            }

            // half table logit part (two 8-half chunks)
            const __half* khp = skh + j * 256 + hb;
#pragma unroll
            for (int c = 0; c < 2; c++) {
                const int co = c << 7;
                H8 a0 = ldt(tKX + r0 + co), a1 = ldt(tKX + r1 + co),
                   a2 = ldt(tKX + r2 + co), a3 = ldt(tKR + r3 + co),
                   a4 = ldt(tKR + r4 + co), a5 = ldt(tKR + r5 + co);
                H8 b0 = ldt(tQX + r0 + co), b1 = ldt(tQX + r1 + co),
                   b2 = ldt(tQX + r2 + co), b3 = ldt(tQR + r3 + co),
                   b4 = ldt(tQR + r4 + co), b5 = ldt(tQR + r5 + co);
                H8 kk = ldt(khp + 8 * c);
                __half2 hq = __float2half2_rn(0.f);
                __half2 hk = hq;
#pragma unroll
                for (int l = 0; l < 4; l++) {
                    __half2 qs = sum6(a0, a1, a2, a3, a4, a5, l);
                    __half2 ks = sum6(b0, b1, b2, b3, b4, b5, l);
                    hq = __hfma2(qh[c * 4 + l], qs, hq);
                    hk = __hfma2(lane(kk, l), ks, hk);
                }
                float2 f = __half22float2(__hadd2(hq, hk));
                facc += f.x + f.y;
            }

            const float a = __expf(facc - bshift);
            ssum += a;

            // value side: fp32 accumulate of a*(v + sum6(vtab)), V fp16 smem
            H8 vva = ldt(svh + j * 256 + hb);
            H8 vvb = ldt(svh + j * 256 + hb + 8);
#pragma unroll
            for (int c = 0; c < 2; c++) {
                const int co = c << 7;
                H8 v0 = ldt(tVX + r0 + co), v1 = ldt(tVX + r1 + co),
                   v2 = ldt(tVX + r2 + co), v3 = ldt(tVR + r3 + co),
                   v4 = ldt(tVR + r4 + co), v5 = ldt(tVR + r5 + co);
                const H8& vv = c ? vvb : vva;
                float* o = of + c * 8;
#pragma unroll
                for (int l = 0; l < 4; l++) {
                    float2 vf = __half22float2(lane(vv, l));
                    float2 tf = __half22float2(sum6(v0, v1, v2, v3, v4, v5, l));
                    o[2 * l + 0] += a * (vf.x + tf.x);
                    o[2 * l + 1] += a * (vf.y + tf.y);
                }
            }
        }

        const float inv = 1.0f / ssum;
        float4* op = (float4*)(g_mid + (size_t)pt * CDIM + hb);
#pragma unroll
        for (int t = 0; t < 4; t++)
            op[t] = make_float4(of[4 * t] * inv, of[4 * t + 1] * inv,
                                of[4 * t + 2] * inv, of[4 * t + 3] * inv);
    }
}

// ---------------------------------------------------------------------------
extern "C" void kernel_launch(void* const* d_in, const int* in_sizes, int n_in,
                              void* d_out, int out_size)
{
    const float* feats    = (const float*)d_in[0];
    const float* n_coords = (const float*)d_in[1];
    const int*   n2n      = (const int*)d_in[2];
    const float* q_xyz    = (const float*)d_in[3];
    const float* k_xyz    = (const float*)d_in[4];
    const float* v_xyz    = (const float*)d_in[5];
    const float* q_rgb    = (const float*)d_in[6];
    const float* k_rgb    = (const float*)d_in[7];
    const float* v_rgb    = (const float*)d_in[8];
    const float* qkv_w    = (const float*)d_in[9];
    const float* qkv_b    = (const float*)d_in[10];
    const float* proj_w   = (const float*)d_in[11];
    const float* proj_b   = (const float*)d_in[12];
    float* out = (float*)d_out;

    float* mid_p = nullptr;
    cudaGetSymbolAddress((void**)&mid_p, g_mid);

    cudaFuncSetAttribute(win_attn, cudaFuncAttributeMaxDynamicSharedMemorySize,
                         ATTN_SMEM_BYTES);

    // 1) table conversion
    cvt_tabs<<<120, 256>>>(k_xyz, q_xyz, v_xyz, k_rgb, q_rgb, v_rgb);

    // 2) QKV projection (fp16 tensor cores; split epilogue -> q fp32, k/v fp16)
    dim3 g1(768 / 128, NPTS / 128);
    gemm_fp16<<<g1, 256>>>(feats, qkv_w, qkv_b, nullptr, NPTS, 768, CDIM, 1);

    // 3) no-op so win_attn is the 4th launch (ncu capture slot)
    nil_k<<<1, 32>>>();

    // 4) windowed attention
    win_attn<<<NWIN, 256, ATTN_SMEM_BYTES>>>(n_coords, n2n);

    // 5) output projection (fp16 tensor cores)
    dim3 g2(CDIM / 128, NPTS / 128);
    gemm_fp16<<<g2, 256>>>(mid_p, proj_w, proj_b, out, NPTS, CDIM, CDIM, 0);
}

// round 16
// speedup vs baseline: 1.0804x; 1.0437x over previous
#include <cuda_runtime.h>
#include <cuda_fp16.h>
#include <mma.h>
#include <math.h>

using namespace nvcuda;

#define NPTS 65536
#define CDIM 256
#define KWIN 32
#define NWIN 2048
#define LXYZ 40
#define LRGB 32
#define QSF 4.0f
#define CQSF 8.0f
#define QK_SCALE 0.25f

// half-table layout offsets (in halfs). Row layout TRANSPOSED: [row][c][h][8]
#define T_KX 0
#define T_QX 30720
#define T_VX 61440
#define T_KR 92160
#define T_QR 116736
#define T_VR 141312
#define T_TOT 165888

// Scratch (allocation-free rule: device globals)
__device__ float g_qkv[(size_t)NPTS * 768];
__device__ __align__(16) __half g_midh[(size_t)NPTS * CDIM];  // attention out, fp16
__device__ __align__(16) __half g_tabh[T_TOT];
__device__ __align__(16) __half g_ah[(size_t)NPTS * 256];     // feats fp16
__device__ __align__(16) __half g_w1h[768 * 256];             // qkv_w fp16
__device__ __align__(16) __half g_w2h[256 * 256];             // proj_w fp16

// ---------------------------------------------------------------------------
// Prep conversions: tables (transposed fp16) + GEMM operands to fp16
// ---------------------------------------------------------------------------
__global__ void cvt_tabs(const float* __restrict__ kx, const float* __restrict__ qx,
                         const float* __restrict__ vx, const float* __restrict__ kr,
                         const float* __restrict__ qr, const float* __restrict__ vr)
{
    int i = blockIdx.x * 256 + threadIdx.x;
    int dst = (i & ~255) | ((i & 8) << 4) | ((i & 240) >> 1) | (i & 7);
    if (i < 30720) {
        g_tabh[T_KX + dst] = __float2half(kx[i]);
        g_tabh[T_QX + dst] = __float2half(qx[i]);
        g_tabh[T_VX + dst] = __float2half(vx[i]);
    }
    if (i < 24576) {
        g_tabh[T_KR + dst] = __float2half(kr[i]);
        g_tabh[T_QR + dst] = __float2half(qr[i]);
        g_tabh[T_VR + dst] = __float2half(vr[i]);
    }
}

// grid-stride fp32 -> fp16 (float2 -> half2)
__global__ void cvt_ops(const float* __restrict__ feats,
                        const float* __restrict__ w1, const float* __restrict__ w2)
{
    const int NA = NPTS * 256 / 2, N1 = 768 * 256 / 2, N2 = 256 * 256 / 2;
    for (int i = blockIdx.x * blockDim.x + threadIdx.x; i < NA;
         i += gridDim.x * blockDim.x) {
        float2 v = ((const float2*)feats)[i];
        ((__half2*)g_ah)[i] = __float22half2_rn(v);
        if (i < N1) {
            float2 u = ((const float2*)w1)[i];
            ((__half2*)g_w1h)[i] = __float22half2_rn(u);
        }
        if (i < N2) {
            float2 u = ((const float2*)w2)[i];
            ((__half2*)g_w2h)[i] = __float22half2_rn(u);
        }
    }
}

// no-op: keeps win_attn at launch #4 (ncu capture slot)
__global__ void nil_k() {}

// ---------------------------------------------------------------------------
// fp16 tensor-core GEMM (fp32 accumulate), fp16 operands from gmem:
// C[M,N] = A[M,K] @ W[N,K]^T + bias[N].  128x128 tile, 8 warps x (32x64),
// BK=32, double-buffered fp16 smem, no in-loop converts.
// ---------------------------------------------------------------------------
#define HS 40   // padded smem row stride (halfs)

__global__ __launch_bounds__(256, 2) void gemm_fp16(
    const __half* __restrict__ A, const __half* __restrict__ Wm,
    const float* __restrict__ bias, float* __restrict__ Cm,
    int M, int N, int Kd)
{
    __shared__ __align__(16) __half As[2][128 * HS];
    __shared__ __align__(16) __half Bs[2][128 * HS];
    __shared__ __align__(16) float scratch[8][256];

    const int tid = threadIdx.x;
    const int wid = tid >> 5;
    const int lane = tid & 31;
    const int brow = blockIdx.y * 128;
    const int bcol = blockIdx.x * 128;
    const int m0 = (wid >> 1) * 32;
    const int n0 = (wid & 1) * 64;

    // loader: 256 threads x 16 halfs (2 x uint4) = 128x32 half tile
    const int lrow = tid >> 1;
    const int lcb = (tid & 1) * 16;
    const __half* Ap = A + (size_t)(brow + lrow) * Kd + lcb;
    const __half* Wp = Wm + (size_t)(bcol + lrow) * Kd + lcb;

    wmma::fragment<wmma::accumulator, 16, 16, 16, float> acc[2][4];
#pragma unroll
    for (int mi = 0; mi < 2; mi++)
#pragma unroll
        for (int ni = 0; ni < 4; ni++) wmma::fill_fragment(acc[mi][ni], 0.f);

    {
        uint4 a0 = *(const uint4*)Ap, a1 = *(const uint4*)(Ap + 8);
        uint4 w0 = *(const uint4*)Wp, w1 = *(const uint4*)(Wp + 8);
        *(uint4*)&As[0][lrow * HS + lcb] = a0;
        *(uint4*)&As[0][lrow * HS + lcb + 8] = a1;
        *(uint4*)&Bs[0][lrow * HS + lcb] = w0;
        *(uint4*)&Bs[0][lrow * HS + lcb + 8] = w1;
    }
    __syncthreads();

    const int nT = Kd / 32;
    for (int kt = 0; kt < nT; kt++) {
        const int buf = kt & 1;
        uint4 a0, a1, w0, w1;
        const bool more = (kt + 1 < nT);
        if (more) {
            const __half* Ax = Ap + (kt + 1) * 32;
            const __half* Wx = Wp + (kt + 1) * 32;
            a0 = *(const uint4*)Ax; a1 = *(const uint4*)(Ax + 8);
            w0 = *(const uint4*)Wx; w1 = *(const uint4*)(Wx + 8);
        }
#pragma unroll
        for (int ks = 0; ks < 2; ks++) {
            wmma::fragment<wmma::matrix_a, 16, 16, 16, __half, wmma::row_major> af[2];
            wmma::fragment<wmma::matrix_b, 16, 16, 16, __half, wmma::col_major> bf[4];
#pragma unroll
            for (int mi = 0; mi < 2; mi++)
                wmma::load_matrix_sync(af[mi],
                    &As[buf][(m0 + 16 * mi) * HS + ks * 16], HS);
#pragma unroll
            for (int ni = 0; ni < 4; ni++)
                wmma::load_matrix_sync(bf[ni],
                    &Bs[buf][(n0 + 16 * ni) * HS + ks * 16], HS);
#pragma unroll
            for (int mi = 0; mi < 2; mi++)
#pragma unroll
                for (int ni = 0; ni < 4; ni++)
                    wmma::mma_sync(acc[mi][ni], af[mi], bf[ni], acc[mi][ni]);
        }
        if (more) {
            const int b2 = buf ^ 1;
            *(uint4*)&As[b2][lrow * HS + lcb] = a0;
            *(uint4*)&As[b2][lrow * HS + lcb + 8] = a1;
            *(uint4*)&Bs[b2][lrow * HS + lcb] = w0;
            *(uint4*)&Bs[b2][lrow * HS + lcb + 8] = w1;
        }
        __syncthreads();
    }

    // epilogue: per-warp scratch, add bias, write out (fp32)
#pragma unroll
    for (int mi = 0; mi < 2; mi++) {
#pragma unroll
        for (int ni = 0; ni < 4; ni++) {
            wmma::store_matrix_sync(scratch[wid], acc[mi][ni], 16,
                                    wmma::mem_row_major);
            __syncwarp();
#pragma unroll
            for (int e = 0; e < 8; e++) {
                int id = e * 32 + lane;
                int rr = id >> 4, cc = id & 15;
                int col = bcol + n0 + 16 * ni + cc;
                Cm[(size_t)(brow + m0 + 16 * mi + rr) * N + col] =
                    scratch[wid][rr * 16 + cc] + __ldg(&bias[col]);
            }
            __syncwarp();
        }
    }
}

// ---------------------------------------------------------------------------
// Windowed attention (round-13 champion, verbatim; only change: fp16 output)
// ---------------------------------------------------------------------------
struct H8 { uint4 u; };
__device__ __forceinline__ H8 ldt(const __half* __restrict__ p) {
    H8 r; r.u = *(const uint4*)p; return r;
}
__device__ __forceinline__ __half2 lane(const H8& a, int l) {
    unsigned w = (l == 0) ? a.u.x : (l == 1) ? a.u.y : (l == 2) ? a.u.z : a.u.w;
    return *reinterpret_cast<const __half2*>(&w);
}
__device__ __forceinline__ __half2 sum6(const H8& a0, const H8& a1, const H8& a2,
                                        const H8& a3, const H8& a4, const H8& a5, int l) {
    return __hadd2(__hadd2(__hadd2(lane(a0, l), lane(a1, l)),
                           __hadd2(lane(a2, l), lane(a3, l))),
                   __hadd2(lane(a4, l), lane(a5, l)));
}

// smem layout (float offsets):
//   sk     [32*320] @ 0       (fp32 K, h-stride 20 -> conflict-free LDS.128)
//   sv     [32*320] @ 10240   (fp32 V, same padding)
//   scoord [192]    @ 20480
//   spt    [32] int @ 20672
//   sidx2  [1024]u2 @ 20704   (2048 floats, ends 22752)
//   skh    [8192]h  @ 22752   (4096 floats, ends 26848)
#define ATTN_SMEM_FLOATS 26848
#define ATTN_SMEM_BYTES (ATTN_SMEM_FLOATS * 4)

__global__ __launch_bounds__(256, 2) void win_attn(
    const float* __restrict__ n_coords, const int* __restrict__ n2n)
{
    extern __shared__ float smem[];
    float* sk = smem;
    float* sv = smem + 10240;
    float* scoord = smem + 20480;
    int* spt = (int*)(smem + 20672);
    uint2* sidx2 = (uint2*)(smem + 20704);
    __half* skh = (__half*)(smem + 22752);

    const int tid = threadIdx.x;
    const int w = blockIdx.x;

    if (tid < KWIN) spt[tid] = n2n[w * KWIN + tid];
    __syncthreads();

    if (tid < 192) {
        int i = tid / 6, d = tid % 6;
        float s = (d < 3) ? QSF : CQSF;
        scoord[tid] = n_coords[(size_t)spt[i] * 6 + d] * s;
    }
    {
        const int h = tid >> 4, c = tid & 15;
        for (int j = 0; j < KWIN; ++j) {
            size_t base = (size_t)spt[j] * 768;
            float kv = g_qkv[base + 256 + tid];
            float vv = g_qkv[base + 512 + tid];
            sk[j * 320 + h * 20 + c] = kv;
            sv[j * 320 + h * 20 + c] = vv;
            skh[j * 256 + tid] = __float2half(kv);
        }
    }
    __syncthreads();

#pragma unroll
    for (int r = 0; r < 4; ++r) {
        int p = r * 256 + tid;
        int i = p >> 5, j = p & 31;
        const float* ci = scoord + i * 6;
        const float* cj = scoord + j * 6;
        int l[6];
#pragma unroll
        for (int d = 0; d < 3; d++) {
            int v = (int)floorf(ci[d] - cj[d]) + LXYZ / 2;
            l[d] = min(max(v, 0), LXYZ - 1);
        }
#pragma unroll
        for (int d = 0; d < 3; d++) {
            int v = (int)floorf(ci[3 + d] - cj[3 + d]) + LRGB / 2;
            l[3 + d] = min(max(v, 0), LRGB - 1);
        }
        unsigned lo = (unsigned)l[0] | ((unsigned)l[1] << 8) |
                      ((unsigned)l[2] << 16) | ((unsigned)l[3] << 24);
        unsigned hi = (unsigned)l[4] | ((unsigned)l[5] << 8);
        sidx2[p] = make_uint2(lo, hi);
    }
    __syncthreads();

    for (int r = 0; r < 2; ++r) {
        const int row = r * 256 + tid;
        const int i = row >> 4;
        const int h = row & 15;
        const int hb = h * 16;
        const int h8 = h * 8;
        const int pt = spt[i];

        const __half* tKX = g_tabh + T_KX + h8;
        const __half* tQX = g_tabh + T_QX + h8;
        const __half* tVX = g_tabh + T_VX + h8;
        const __half* tKR = g_tabh + T_KR + h8;
        const __half* tQR = g_tabh + T_QR + h8;
        const __half* tVR = g_tabh + T_VR + h8;

        float qf[16];
        __half2 qh[8];
        {
            const float4* qp = (const float4*)(g_qkv + (size_t)pt * 768 + hb);
#pragma unroll
            for (int t = 0; t < 4; t++) {
                float4 v = qp[t];
                qf[t * 4 + 0] = v.x * QK_SCALE; qf[t * 4 + 1] = v.y * QK_SCALE;
                qf[t * 4 + 2] = v.z * QK_SCALE; qf[t * 4 + 3] = v.w * QK_SCALE;
            }
#pragma unroll
            for (int k = 0; k < 8; k++)
                qh[k] = __floats2half2_rn(qf[2 * k], qf[2 * k + 1]);
        }

        float bshift = 0.f;
        {
            const float* k0 = sk + h * 20;
#pragma unroll
            for (int t = 0; t < 4; t++) {
                float4 kv = *(const float4*)(k0 + 4 * t);
                bshift += qf[4 * t + 0] * kv.x + qf[4 * t + 1] * kv.y +
                          qf[4 * t + 2] * kv.z + qf[4 * t + 3] * kv.w;
            }
        }

        float ssum = 0.f;
        float of[16];
#pragma unroll
        for (int e = 0; e < 16; e++) of[e] = 0.f;

        for (int j = 0; j < KWIN; ++j) {
            const uint2 pk = sidx2[i * 32 + j];
            const int r0 = (int)(pk.x & 255) << 8;
            const int r1 = (int)(40 + ((pk.x >> 8) & 255)) << 8;
            const int r2 = (int)(80 + ((pk.x >> 16) & 255)) << 8;
            const int r3 = (int)(pk.x >> 24) << 8;
            const int r4 = (int)(32 + (pk.y & 255)) << 8;
            const int r5 = (int)(64 + ((pk.y >> 8) & 255)) << 8;

            const float* kj = sk + j * 320 + h * 20;
            float facc = 0.f;
#pragma unroll
            for (int t = 0; t < 4; t++) {
                float4 kv = *(const float4*)(kj + 4 * t);
                facc += qf[4 * t + 0] * kv.x + qf[4 * t + 1] * kv.y +
                        qf[4 * t + 2] * kv.z + qf[4 * t + 3] * kv.w;
            }

            const __half* khp = skh + j * 256 + hb;
#pragma unroll
            for (int c = 0; c < 2; c++) {
                const int co = c << 7;
                H8 a0 = ldt(tKX + r0 + co), a1 = ldt(tKX + r1 + co),
                   a2 = ldt(tKX + r2 + co), a3 = ldt(tKR + r3 + co),
                   a4 = ldt(tKR + r4 + co), a5 = ldt(tKR + r5 + co);
                H8 b0 = ldt(tQX + r0 + co), b1 = ldt(tQX + r1 + co),
                   b2 = ldt(tQX + r2 + co), b3 = ldt(tQR + r3 + co),
                   b4 = ldt(tQR + r4 + co), b5 = ldt(tQR + r5 + co);
                H8 kk = ldt(khp + 8 * c);
                __half2 hq = __float2half2_rn(0.f);
                __half2 hk = hq;
#pragma unroll
                for (int l = 0; l < 4; l++) {
                    __half2 qs = sum6(a0, a1, a2, a3, a4, a5, l);
                    __half2 ks = sum6(b0, b1, b2, b3, b4, b5, l);
                    hq = __hfma2(qh[c * 4 + l], qs, hq);
                    hk = __hfma2(lane(kk, l), ks, hk);
                }
                float2 f = __half22float2(__hadd2(hq, hk));
                facc += f.x + f.y;
            }

            const float a = __expf(facc - bshift);
            ssum += a;

            const float* vj = sv + j * 320 + h * 20;
#pragma unroll
            for (int c = 0; c < 2; c++) {
                const int co = c << 7;
                H8 v0 = ldt(tVX + r0 + co), v1 = ldt(tVX + r1 + co),
                   v2 = ldt(tVX + r2 + co), v3 = ldt(tVR + r3 + co),
                   v4 = ldt(tVR + r4 + co), v5 = ldt(tVR + r5 + co);
                float4 va = *(const float4*)(vj + 8 * c);
                float4 vb = *(const float4*)(vj + 8 * c + 4);
                float2 t0 = __half22float2(sum6(v0, v1, v2, v3, v4, v5, 0));
                float2 t1 = __half22float2(sum6(v0, v1, v2, v3, v4, v5, 1));
                float2 t2 = __half22float2(sum6(v0, v1, v2, v3, v4, v5, 2));
                float2 t3 = __half22float2(sum6(v0, v1, v2, v3, v4, v5, 3));
                float* o = of + c * 8;
                o[0] += a * (va.x + t0.x); o[1] += a * (va.y + t0.y);
                o[2] += a * (va.z + t1.x); o[3] += a * (va.w + t1.y);
                o[4] += a * (vb.x + t2.x); o[5] += a * (vb.y + t2.y);
                o[6] += a * (vb.z + t3.x); o[7] += a * (vb.w + t3.y);
            }
        }

        const float inv = 1.0f / ssum;
        // write output as fp16 (same rounding the proj GEMM applied before)
        __half2* op = (__half2*)(g_midh + (size_t)pt * CDIM + hb);
#pragma unroll
        for (int k = 0; k < 8; k++)
            op[k] = __floats2half2_rn(of[2 * k] * inv, of[2 * k + 1] * inv);
    }
}

// ---------------------------------------------------------------------------
extern "C" void kernel_launch(void* const* d_in, const int* in_sizes, int n_in,
                              void* d_out, int out_size)
{
    const float* feats    = (const float*)d_in[0];
    const float* n_coords = (const float*)d_in[1];
    const int*   n2n      = (const int*)d_in[2];
    const float* q_xyz    = (const float*)d_in[3];
    const float* k_xyz    = (const float*)d_in[4];
    const float* v_xyz    = (const float*)d_in[5];
    const float* q_rgb    = (const float*)d_in[6];
    const float* k_rgb    = (const float*)d_in[7];
    const float* v_rgb    = (const float*)d_in[8];
    const float* qkv_w    = (const float*)d_in[9];
    const float* qkv_b    = (const float*)d_in[10];
    const float* proj_w   = (const float*)d_in[11];
    const float* proj_b   = (const float*)d_in[12];
    float* out = (float*)d_out;

    float* qkv_p = nullptr;
    __half *ah_p = nullptr, *w1_p = nullptr, *w2_p = nullptr, *midh_p = nullptr;
    cudaGetSymbolAddress((void**)&qkv_p, g_qkv);
    cudaGetSymbolAddress((void**)&ah_p, g_ah);
    cudaGetSymbolAddress((void**)&w1_p, g_w1h);
    cudaGetSymbolAddress((void**)&w2_p, g_w2h);
    cudaGetSymbolAddress((void**)&midh_p, g_midh);

    cudaFuncSetAttribute(win_attn, cudaFuncAttributeMaxDynamicSharedMemorySize,
                         ATTN_SMEM_BYTES);

    // 1) prep conversions (tables + fp16 GEMM operands)
    cvt_tabs<<<120, 256>>>(k_xyz, q_xyz, v_xyz, k_rgb, q_rgb, v_rgb);
    cvt_ops<<<2048, 256>>>(feats, qkv_w, proj_w);

    // 2) QKV projection (fp16 operands, fp32 accumulate/out)
    dim3 g1(768 / 128, NPTS / 128);
    gemm_fp16<<<g1, 256>>>(ah_p, w1_p, qkv_b, qkv_p, NPTS, 768, CDIM);

    // 3) (slot alignment retired its purpose; keep win_attn at #4)
    nil_k<<<1, 32>>>();

    // 4) windowed attention (round-13 core; fp16 output)
    win_attn<<<NWIN, 256, ATTN_SMEM_BYTES>>>(n_coords, n2n);

    // 5) output projection (fp16 operands; fp32 out to d_out)
    dim3 g2(CDIM / 128, NPTS / 128);
    gemm_fp16<<<g2, 256>>>(midh_p, w2_p, proj_b, out, NPTS, CDIM, CDIM);
}